// round 15
// baseline (speedup 1.0000x reference)
#include <cuda_runtime.h>
#include <cuda_fp16.h>
#include <math.h>
#include <stdint.h>

#define NBR 4
#define Dd 256
#define SDIM 64
#define MEAS 320
#define MH 128
#define RH 64
#define UD 16
#define NOBS 25
#define BSZ 32768
#define HALL 512
#define K3 272
#define N2 288
#define TM 64

__device__ __half g_W1h[HALL * MEAS];
__device__ __half g_W1l[HALL * MEAS];
__device__ __half g_W2h[Dd * MH];
__device__ __half g_W2l[Dd * MH];
__device__ __half g_B3h[N2 * K3];
__device__ __half g_B3l[N2 * K3];

// ---- smem layout (bytes) ----
#define HSTR 1072
#define HP   68608                 // 64*1072
#define OFF_BB 137216
#define BBUF 27648                 // 2 planes x 288 x 48
#define BPL  13824
#define OFF_AB 192512              // 2 bufs x 2 planes x 64 x 48
#define ABUF 6144
#define APL  3072
#define OFF_SU 204800              // u*dt floats [64][16]
#define OFF_LN 208896              // LN scratch 2 x 256 floats
#define SMEM_TOTAL 210944

#define CPA(dst, src) asm volatile("cp.async.cg.shared.global [%0], [%1], 16;" :: "r"(dst), "l"(src))
#define CPC()  asm volatile("cp.async.commit_group;")
#define CPW1() asm volatile("cp.async.wait_group 1;")
#define CPW0() asm volatile("cp.async.wait_group 0;")

#define LDSM4(r, a) \
    asm volatile("ldmatrix.sync.aligned.m8n8.x4.shared.b16 {%0,%1,%2,%3}, [%4];" \
        : "=r"((r)[0]), "=r"((r)[1]), "=r"((r)[2]), "=r"((r)[3]) : "r"(a))
#define LDSM2(r, a) \
    asm volatile("ldmatrix.sync.aligned.m8n8.x2.shared.b16 {%0,%1}, [%2];" \
        : "=r"((r)[0]), "=r"((r)[1]) : "r"(a))

__device__ __forceinline__ void mma_f32(float* d, const uint32_t* a, const uint32_t* b) {
    asm volatile(
        "mma.sync.aligned.m16n8k16.row.col.f32.f16.f16.f32 "
        "{%0,%1,%2,%3},{%4,%5,%6,%7},{%8,%9},{%0,%1,%2,%3};\n"
        : "+f"(d[0]), "+f"(d[1]), "+f"(d[2]), "+f"(d[3])
        : "r"(a[0]), "r"(a[1]), "r"(a[2]), "r"(a[3]), "r"(b[0]), "r"(b[1]));
}
__device__ __forceinline__ void mma_f16(uint32_t* d, const uint32_t* a, const uint32_t* b) {
    asm volatile(
        "mma.sync.aligned.m16n8k16.row.col.f16.f16.f16.f16 "
        "{%0,%1},{%2,%3,%4,%5},{%6,%7},{%0,%1};\n"
        : "+r"(d[0]), "+r"(d[1])
        : "r"(a[0]), "r"(a[1]), "r"(a[2]), "r"(a[3]), "r"(b[0]), "r"(b[1]));
}
__device__ __forceinline__ void addcorr(float* a, const uint32_t* c) {
    float2 x = __half22float2(*(const half2*)&c[0]);
    float2 y = __half22float2(*(const half2*)&c[1]);
    a[0] += x.x; a[1] += x.y; a[2] += y.x; a[3] += y.y;
}
__device__ __forceinline__ void splith(float v, __half& hi, __half& lo) {
    hi = __float2half_rn(v);
    lo = __float2half_rn(v - __half2float(hi));
}
__device__ __forceinline__ uint32_t packh(__half a, __half b) {
    return (uint32_t)__half_as_ushort(a) | ((uint32_t)__half_as_ushort(b) << 16);
}
__device__ __forceinline__ uint32_t smem_u32(const void* p) {
    uint32_t a;
    asm("{ .reg .u64 t; cvta.to.shared.u64 t, %1; cvt.u32.u64 %0, t; }" : "=r"(a) : "l"(p));
    return a;
}

// ======================= precompute (unchanged, known-correct) =======================
__global__ void preK(const float* __restrict__ W1, const float* __restrict__ gates,
                     const float* __restrict__ W2, const float* __restrict__ Wout,
                     const float* __restrict__ Bmat, const float* __restrict__ C,
                     const float* __restrict__ Dm) {
    int bid = blockIdx.x, tid = threadIdx.x;
    if (bid < 640) {
        int e = bid * 256 + tid;
        int row = e / MEAS, k = e % MEAS, n = row >> 7;
        float sc = 1.f;
        if (k < Dd) sc = 1.f / (1.f + expf(-gates[n * Dd + k]));
        splith(W1[e] * sc, g_W1h[e], g_W1l[e]);
    } else if (bid < 768) {
        int e = (bid - 640) * 256 + tid;
        splith(W2[e], g_W2h[e], g_W2l[e]);
    } else if (bid < 1040) {
        int e = (bid - 768) * 256 + tid;
        int d = e / K3, c = e % K3;
        float s = 0.f;
        if (c < 256) {
            int n = c >> 6, j = c & 63;
            const float* wr = Wout + (n * Dd + d) * RH;
            const float* br = Bmat + n * RH * (RH + UD) + j;
            #pragma unroll 8
            for (int r = 0; r < RH; r++) s += wr[r] * br[r * (RH + UD)];
        } else {
            int u = c - 256;
            for (int n = 0; n < NBR; n++) {
                const float* wr = Wout + (n * Dd + d) * RH;
                const float* br = Bmat + n * RH * (RH + UD) + RH + u;
                #pragma unroll 8
                for (int r = 0; r < RH; r++) s += wr[r] * br[r * (RH + UD)];
            }
        }
        splith(s, g_B3h[e], g_B3l[e]);
    } else if (bid < 1040 + NOBS) {
        int o = bid - 1040;
        __shared__ float sCW[256];
        {
            int n = tid >> 6, r = tid & 63;
            const float* cr = C + o * Dd;
            const float* wp = Wout + n * Dd * RH + r;
            float s = 0.f;
            #pragma unroll 8
            for (int d = 0; d < Dd; d++) s += cr[d] * wp[d * RH];
            sCW[tid] = s;
        }
        __syncthreads();
        for (int c = tid; c < K3; c += 256) {
            float v;
            if (c < 256) {
                int n = c >> 6, j = c & 63;
                const float* br = Bmat + n * RH * (RH + UD) + j;
                v = 0.f;
                #pragma unroll 8
                for (int r = 0; r < RH; r++) v += sCW[n * 64 + r] * br[r * (RH + UD)];
            } else {
                int u = c - 256;
                v = Dm[o * UD + u];
                for (int n = 0; n < NBR; n++) {
                    const float* br = Bmat + n * RH * (RH + UD) + RH + u;
                    #pragma unroll 8
                    for (int r = 0; r < RH; r++) v += sCW[n * 64 + r] * br[r * (RH + UD)];
                }
            }
            splith(v, g_B3h[(256 + o) * K3 + c], g_B3l[(256 + o) * K3 + c]);
        }
    } else {
        int e = (bid - 1040 - NOBS) * 256 + tid;
        if (e < (N2 - 256 - NOBS) * K3) {
            int r = 256 + NOBS + e / K3, c = e % K3;
            g_B3h[r * K3 + c] = __float2half(0.f);
            g_B3l[r * K3 + c] = __float2half(0.f);
        }
    }
}

// ======================= main kernel: 512 threads, 4 warps/SMSP =======================
__global__ __launch_bounds__(512, 1) void skolr6(
    const float* __restrict__ z_dyn, const float* __restrict__ z_static,
    const float* __restrict__ dtp,   const float* __restrict__ ut,
    const float* __restrict__ b1g,   const float* __restrict__ gammag,
    const float* __restrict__ betag, const float* __restrict__ b2g,
    float* __restrict__ out)
{
    extern __shared__ char sm[];
    const uint32_t smb = smem_u32(sm);
    const int tid = threadIdx.x, w = tid >> 5, lane = tid & 31;
    const int wm = w >> 2, wn = w & 3;          // 4M x 4N warp grid
    const int g = lane >> 2, t4 = lane & 3;
    const int row0 = blockIdx.x * TM;
    const float dt = dtp[0];

    const int sub = lane >> 3;
    const uint32_t aRow = ((uint32_t)(sub & 1)) * 8 + (lane & 7);
    const uint32_t aCh  = ((uint32_t)(sub >> 1)) * 16;
    const uint32_t bRow = ((uint32_t)(sub >> 1)) * 8 + (lane & 7);
    const uint32_t bCh  = ((uint32_t)(sub & 1)) * 16;

    float* su  = (float*)(sm + OFF_SU);
    float* lns = (float*)(sm + OFF_LN);         // [4][64]
    float* lnq = lns + 256;

    if (tid < 256) {
        int m = tid >> 2, q = tid & 3;
        float4 f = *(const float4*)&ut[(size_t)(row0 + m) * UD + q * 4];
        f.x *= dt; f.y *= dt; f.z *= dt; f.w *= dt;
        *(float4*)&su[m * UD + q * 4] = f;
    }

    // ================= GEMM1 (2 halves of 256 cols) + fused LN/GELU =================
    for (int p = 0; p < 2; p++) {
        float acc[8][4];
        uint32_t corr[8][2];
        #pragma unroll
        for (int i = 0; i < 8; i++) {
            acc[i][0] = acc[i][1] = acc[i][2] = acc[i][3] = 0.f;
            corr[i][0] = corr[i][1] = 0u;
        }

        #define STAGE1(kc_, buf_) do { \
            int _kc = (kc_), _bf = (buf_); \
            if (tid < 256) { int m = tid >> 2, q = tid & 3; \
              float4 f = (_kc < 16) \
                ? *(const float4*)&z_dyn[(size_t)(row0 + m) * Dd + _kc * 16 + q * 4] \
                : *(const float4*)&z_static[(size_t)(row0 + m) * SDIM + (_kc - 16) * 16 + q * 4]; \
              __half h0, l0, h1, l1, h2, l2, h3, l3; \
              splith(f.x, h0, l0); splith(f.y, h1, l1); splith(f.z, h2, l2); splith(f.w, h3, l3); \
              uint2 hp, lp; \
              hp.x = packh(h0, h1); hp.y = packh(h2, h3); \
              lp.x = packh(l0, l1); lp.y = packh(l2, l3); \
              char* ab = sm + OFF_AB + _bf * ABUF + m * 48 + q * 8; \
              *(uint2*)ab = hp; *(uint2*)(ab + APL) = lp; } \
            _Pragma("unroll") \
            for (int t = 0; t < 2; t++) { \
                int comp = tid + t * 512; \
                int n = comp & 255, h16 = (comp >> 8) & 1, pl = comp >> 9; \
                const __half* src = (pl ? g_W1l : g_W1h) + (size_t)(p * 256 + n) * MEAS + _kc * 16 + h16 * 8; \
                uint32_t dst = smb + OFF_BB + _bf * BBUF + pl * BPL + n * 48 + h16 * 16; \
                CPA(dst, src); \
            } \
        } while (0)

        STAGE1(0, 0); CPC();
        for (int kc = 0; kc < 20; kc++) {
            if (kc < 19) { STAGE1(kc + 1, (kc + 1) & 1); CPC(); CPW1(); } else { CPW0(); }
            __syncthreads();
            const int buf = kc & 1;
            uint32_t ah[4], al[4];
            uint32_t aaddr = smb + OFF_AB + buf * ABUF + (wm * 16 + aRow) * 48 + aCh;
            LDSM4(ah, aaddr); LDSM4(al, aaddr + APL);
            uint32_t bbase = smb + OFF_BB + buf * BBUF + (wn * 64 + bRow) * 48 + bCh;
            #pragma unroll
            for (int q = 0; q < 4; q++) {
                uint32_t bh[4], bl[4];
                uint32_t ba = bbase + q * (16 * 48);
                LDSM4(bh, ba); LDSM4(bl, ba + BPL);
                mma_f32(acc[q * 2],      ah, bh);
                mma_f16(corr[q * 2],     ah, bl);
                mma_f16(corr[q * 2],     al, bh);
                mma_f32(acc[q * 2 + 1],  ah, bh + 2);
                mma_f16(corr[q * 2 + 1], ah, bl + 2);
                mma_f16(corr[q * 2 + 1], al, bh + 2);
            }
            __syncthreads();
        }
        #undef STAGE1

        // ---- epilogue: +corr, +b1, LN(128) (t4 shuffles + warp-pair smem), GELU -> H ----
        float s0 = 0.f, q0 = 0.f, s1 = 0.f, q1 = 0.f;
        #pragma unroll
        for (int nt = 0; nt < 8; nt++) {
            addcorr(acc[nt], corr[nt]);
            int c = p * 256 + wn * 64 + nt * 8 + t4 * 2;
            float2 bv = __ldg((const float2*)&b1g[c]);
            acc[nt][0] += bv.x; acc[nt][1] += bv.y; acc[nt][2] += bv.x; acc[nt][3] += bv.y;
            s0 += acc[nt][0] + acc[nt][1];
            q0 = fmaf(acc[nt][0], acc[nt][0], fmaf(acc[nt][1], acc[nt][1], q0));
            s1 += acc[nt][2] + acc[nt][3];
            q1 = fmaf(acc[nt][2], acc[nt][2], fmaf(acc[nt][3], acc[nt][3], q1));
        }
        #pragma unroll
        for (int o = 1; o <= 2; o <<= 1) {
            s0 += __shfl_xor_sync(0xffffffffu, s0, o);
            q0 += __shfl_xor_sync(0xffffffffu, q0, o);
            s1 += __shfl_xor_sync(0xffffffffu, s1, o);
            q1 += __shfl_xor_sync(0xffffffffu, q1, o);
        }
        const int rA = wm * 16 + g, rB = rA + 8;
        if (t4 == 0) {
            lns[wn * 64 + rA] = s0; lnq[wn * 64 + rA] = q0;
            lns[wn * 64 + rB] = s1; lnq[wn * 64 + rB] = q1;
        }
        __syncthreads();
        const int pw = wn ^ 1;
        float s0t = s0 + lns[pw * 64 + rA], q0t = q0 + lnq[pw * 64 + rA];
        float s1t = s1 + lns[pw * 64 + rB], q1t = q1 + lnq[pw * 64 + rB];
        const float mean0 = s0t * (1.f / 128.f);
        const float inv0  = rsqrtf(q0t * (1.f / 128.f) - mean0 * mean0 + 1e-5f);
        const float mean1 = s1t * (1.f / 128.f);
        const float inv1  = rsqrtf(q1t * (1.f / 128.f) - mean1 * mean1 + 1e-5f);
        #pragma unroll
        for (int nt = 0; nt < 8; nt++) {
            int c = p * 256 + wn * 64 + nt * 8 + t4 * 2;
            float2 gv = __ldg((const float2*)&gammag[c]);
            float2 ev = __ldg((const float2*)&betag[c]);
            float t0 = (acc[nt][0] - mean0) * inv0 * gv.x + ev.x;
            float t1 = (acc[nt][1] - mean0) * inv0 * gv.y + ev.y;
            float t2 = (acc[nt][2] - mean1) * inv1 * gv.x + ev.x;
            float t3 = (acc[nt][3] - mean1) * inv1 * gv.y + ev.y;
            t0 = 0.5f * t0 * (1.f + erff(t0 * 0.70710678118654752f));
            t1 = 0.5f * t1 * (1.f + erff(t1 * 0.70710678118654752f));
            t2 = 0.5f * t2 * (1.f + erff(t2 * 0.70710678118654752f));
            t3 = 0.5f * t3 * (1.f + erff(t3 * 0.70710678118654752f));
            __half x0, y0, x1, y1, x2, y2, x3, y3;
            splith(t0, x0, y0); splith(t1, x1, y1); splith(t2, x2, y2); splith(t3, x3, y3);
            *(uint32_t*)(sm + rA * HSTR + c * 2)      = packh(x0, x1);
            *(uint32_t*)(sm + HP + rA * HSTR + c * 2) = packh(y0, y1);
            *(uint32_t*)(sm + rB * HSTR + c * 2)      = packh(x2, x3);
            *(uint32_t*)(sm + HP + rB * HSTR + c * 2) = packh(y2, y3);
        }
        __syncthreads();
    }

    // ================= stage-1: G[n] = H[n] @ W2[n]^T + b2 (warp wn = branch wn) =================
    float acc1[8][4];
    uint32_t corr1[8][2];
    #pragma unroll
    for (int i = 0; i < 8; i++) {
        acc1[i][0] = acc1[i][1] = acc1[i][2] = acc1[i][3] = 0.f;
        corr1[i][0] = corr1[i][1] = 0u;
    }

    #define STAGEW2(kc_, buf_) do { \
        int _kc = (kc_), _bf = (buf_); \
        _Pragma("unroll") \
        for (int t = 0; t < 2; t++) { \
            int comp = tid + t * 512; \
            int n = comp & 255, h16 = (comp >> 8) & 1, pl = comp >> 9; \
            const __half* src = (pl ? g_W2l : g_W2h) + (size_t)n * MH + _kc * 16 + h16 * 8; \
            uint32_t dst = smb + OFF_BB + _bf * BBUF + pl * BPL + n * 48 + h16 * 16; \
            CPA(dst, src); \
        } \
    } while (0)

    STAGEW2(0, 0); CPC();
    for (int kc = 0; kc < 8; kc++) {
        if (kc < 7) { STAGEW2(kc + 1, (kc + 1) & 1); CPC(); CPW1(); } else { CPW0(); }
        __syncthreads();
        const int buf = kc & 1;
        uint32_t ah[4], al[4];
        uint32_t aaddr = smb + (wm * 16 + aRow) * HSTR + wn * 256 + kc * 32 + aCh;
        LDSM4(ah, aaddr); LDSM4(al, aaddr + HP);
        uint32_t bbase = smb + OFF_BB + buf * BBUF + (wn * 64 + bRow) * 48 + bCh;
        #pragma unroll
        for (int q = 0; q < 4; q++) {
            uint32_t bh[4], bl[4];
            uint32_t ba = bbase + q * (16 * 48);
            LDSM4(bh, ba); LDSM4(bl, ba + BPL);
            mma_f32(acc1[q * 2],      ah, bh);
            mma_f16(corr1[q * 2],     ah, bl);
            mma_f16(corr1[q * 2],     al, bh);
            mma_f32(acc1[q * 2 + 1],  ah, bh + 2);
            mma_f16(corr1[q * 2 + 1], ah, bl + 2);
            mma_f16(corr1[q * 2 + 1], al, bh + 2);
        }
        __syncthreads();
    }
    #undef STAGEW2

    // ---- stage-1 epilogue: +corr, +b2, split G -> H cols 0..255; u -> cols 256..271 ----
    {
        const int rA = wm * 16 + g, rB = rA + 8;
        #pragma unroll
        for (int nt = 0; nt < 8; nt++) {
            addcorr(acc1[nt], corr1[nt]);
            int c = wn * 64 + nt * 8 + t4 * 2;
            float2 bv = __ldg((const float2*)&b2g[c]);
            float v0 = acc1[nt][0] + bv.x, v1 = acc1[nt][1] + bv.y;
            float v2 = acc1[nt][2] + bv.x, v3 = acc1[nt][3] + bv.y;
            __half x0, y0, x1, y1, x2, y2, x3, y3;
            splith(v0, x0, y0); splith(v1, x1, y1); splith(v2, x2, y2); splith(v3, x3, y3);
            *(uint32_t*)(sm + rA * HSTR + c * 2)      = packh(x0, x1);
            *(uint32_t*)(sm + HP + rA * HSTR + c * 2) = packh(y0, y1);
            *(uint32_t*)(sm + rB * HSTR + c * 2)      = packh(x2, x3);
            *(uint32_t*)(sm + HP + rB * HSTR + c * 2) = packh(y2, y3);
        }
        for (int idx = tid; idx < TM * UD; idx += 512) {
            int m = idx >> 4, cu = idx & 15;
            __half hi, lo; splith(su[m * UD + cu], hi, lo);
            *(__half*)(sm + m * HSTR + 512 + cu * 2)      = hi;
            *(__half*)(sm + HP + m * HSTR + 512 + cu * 2) = lo;
        }
    }
    __syncthreads();

    // ================= stage-2: [z|yt][64][288] = [G|u][64][272] x B3^T =================
    float acc2[9][4];
    uint32_t corr2[9][2];
    #pragma unroll
    for (int i = 0; i < 9; i++) {
        acc2[i][0] = acc2[i][1] = acc2[i][2] = acc2[i][3] = 0.f;
        corr2[i][0] = corr2[i][1] = 0u;
    }

    #define STAGE3(kc_, buf_) do { \
        int _kc = (kc_), _bf = (buf_); \
        for (int idx = tid; idx < 1152; idx += 512) { \
            int pl = idx / 576, rem = idx % 576, n = rem >> 1, h16 = rem & 1; \
            const __half* src = (pl ? g_B3l : g_B3h) + (size_t)n * K3 + _kc * 16 + h16 * 8; \
            uint32_t dst = smb + OFF_BB + _bf * BBUF + pl * BPL + n * 48 + h16 * 16; \
            CPA(dst, src); \
        } \
    } while (0)

    STAGE3(0, 0); CPC();
    for (int kc = 0; kc < 17; kc++) {
        if (kc < 16) { STAGE3(kc + 1, (kc + 1) & 1); CPC(); CPW1(); } else { CPW0(); }
        __syncthreads();
        const int buf = kc & 1;
        uint32_t ah[4], al[4];
        uint32_t aaddr = smb + (wm * 16 + aRow) * HSTR + kc * 32 + aCh;
        LDSM4(ah, aaddr); LDSM4(al, aaddr + HP);
        uint32_t bbase = smb + OFF_BB + buf * BBUF + (wn * 72 + bRow) * 48 + bCh;
        #pragma unroll
        for (int q = 0; q < 4; q++) {
            uint32_t bh[4], bl[4];
            uint32_t ba = bbase + q * (16 * 48);
            LDSM4(bh, ba); LDSM4(bl, ba + BPL);
            mma_f32(acc2[q * 2],      ah, bh);
            mma_f16(corr2[q * 2],     ah, bl);
            mma_f16(corr2[q * 2],     al, bh);
            mma_f32(acc2[q * 2 + 1],  ah, bh + 2);
            mma_f16(corr2[q * 2 + 1], ah, bl + 2);
            mma_f16(corr2[q * 2 + 1], al, bh + 2);
        }
        {   // remainder 8-row tile (rows wn*72+64 .. +71)
            uint32_t ra = smb + OFF_BB + buf * BBUF +
                          (wn * 72 + 64 + (lane & 7)) * 48 + ((lane >> 3) & 1) * 16;
            uint32_t bh[2], bl[2];
            LDSM2(bh, ra); LDSM2(bl, ra + BPL);
            mma_f32(acc2[8],  ah, bh);
            mma_f16(corr2[8], ah, bl);
            mma_f16(corr2[8], al, bh);
        }
        __syncthreads();
    }
    #undef STAGE3

    // ---- epilogue: write z_next and yt (biases fully folded) ----
    float* out_yt = out + (size_t)BSZ * Dd;
    #pragma unroll
    for (int nt = 0; nt < 9; nt++) {
        addcorr(acc2[nt], corr2[nt]);
        const int n0 = wn * 72 + nt * 8 + t4 * 2;
        const int r = wm * 16 + g;
        float v0 = acc2[nt][0], v1 = acc2[nt][1];
        float v2 = acc2[nt][2], v3 = acc2[nt][3];
        if (n0 < Dd) {
            *(float2*)&out[(size_t)(row0 + r) * Dd + n0]     = make_float2(v0, v1);
            *(float2*)&out[(size_t)(row0 + r + 8) * Dd + n0] = make_float2(v2, v3);
        } else {
            const int o = n0 - Dd;
            if (o < NOBS)     { out_yt[(size_t)(row0 + r) * NOBS + o]     = v0;
                                out_yt[(size_t)(row0 + r + 8) * NOBS + o] = v2; }
            if (o + 1 < NOBS) { out_yt[(size_t)(row0 + r) * NOBS + o + 1]     = v1;
                                out_yt[(size_t)(row0 + r + 8) * NOBS + o + 1] = v3; }
        }
    }
}

extern "C" void kernel_launch(void* const* d_in, const int* in_sizes, int n_in,
                              void* d_out, int out_size) {
    const float* z_dyn    = (const float*)d_in[0];
    const float* z_static = (const float*)d_in[1];
    const float* dt       = (const float*)d_in[2];
    const float* ut       = (const float*)d_in[3];
    const float* gates    = (const float*)d_in[4];
    const float* W1       = (const float*)d_in[5];
    const float* b1       = (const float*)d_in[6];
    const float* gamma    = (const float*)d_in[7];
    const float* beta     = (const float*)d_in[8];
    const float* W2       = (const float*)d_in[9];
    const float* b2       = (const float*)d_in[10];
    const float* Bmat     = (const float*)d_in[13];
    const float* Wout     = (const float*)d_in[14];
    const float* Cmat     = (const float*)d_in[15];
    const float* Dm       = (const float*)d_in[16];
    float* out = (float*)d_out;

    preK<<<1040 + NOBS + 8, 256>>>(W1, gates, W2, Wout, Bmat, Cmat, Dm);

    cudaFuncSetAttribute(skolr6, cudaFuncAttributeMaxDynamicSharedMemorySize, SMEM_TOTAL);
    skolr6<<<BSZ / TM, 512, SMEM_TOTAL>>>(z_dyn, z_static, dt, ut, b1, gamma, beta, b2, out);
}

// round 16
// speedup vs baseline: 1.0316x; 1.0316x over previous
#include <cuda_runtime.h>
#include <cuda_fp16.h>
#include <math.h>
#include <stdint.h>

#define NBR 4
#define Dd 256
#define SDIM 64
#define MEAS 320
#define MH 128
#define RH 64
#define UD 16
#define NOBS 25
#define BSZ 32768
#define HALL 512
#define K3 272
#define N2 288
#define TM 64

__device__ __half g_W1h[HALL * MEAS];
__device__ __half g_W1l[HALL * MEAS];
__device__ __half g_W2h[Dd * MH];
__device__ __half g_W2l[Dd * MH];
__device__ __half g_B3h[N2 * K3];
__device__ __half g_B3l[N2 * K3];

// ---- smem layout (bytes) ----
#define HSTR 1072
#define HP   68608                 // 64*1072
#define OFF_BB 137216
#define BBUF 27648                 // 2 planes x 288 x 48
#define BPL  13824
#define OFF_AB 192512              // 2 bufs x 2 planes x 64 x 48
#define ABUF 6144
#define APL  3072
#define OFF_SU 204800              // u*dt floats [64][16]
#define OFF_LN 208896              // LN scratch 2 x 256 floats
#define SMEM_TOTAL 210944

#define CPA(dst, src) asm volatile("cp.async.cg.shared.global [%0], [%1], 16;" :: "r"(dst), "l"(src))
#define CPC()  asm volatile("cp.async.commit_group;")
#define CPW1() asm volatile("cp.async.wait_group 1;")
#define CPW0() asm volatile("cp.async.wait_group 0;")

#define LDSM4(r, a) \
    asm volatile("ldmatrix.sync.aligned.m8n8.x4.shared.b16 {%0,%1,%2,%3}, [%4];" \
        : "=r"((r)[0]), "=r"((r)[1]), "=r"((r)[2]), "=r"((r)[3]) : "r"(a))
#define LDSM2(r, a) \
    asm volatile("ldmatrix.sync.aligned.m8n8.x2.shared.b16 {%0,%1}, [%2];" \
        : "=r"((r)[0]), "=r"((r)[1]) : "r"(a))

__device__ __forceinline__ void mma_f32(float* d, const uint32_t* a, const uint32_t* b) {
    asm volatile(
        "mma.sync.aligned.m16n8k16.row.col.f32.f16.f16.f32 "
        "{%0,%1,%2,%3},{%4,%5,%6,%7},{%8,%9},{%0,%1,%2,%3};\n"
        : "+f"(d[0]), "+f"(d[1]), "+f"(d[2]), "+f"(d[3])
        : "r"(a[0]), "r"(a[1]), "r"(a[2]), "r"(a[3]), "r"(b[0]), "r"(b[1]));
}
__device__ __forceinline__ void mma_f16(uint32_t* d, const uint32_t* a, const uint32_t* b) {
    asm volatile(
        "mma.sync.aligned.m16n8k16.row.col.f16.f16.f16.f16 "
        "{%0,%1},{%2,%3,%4,%5},{%6,%7},{%0,%1};\n"
        : "+r"(d[0]), "+r"(d[1])
        : "r"(a[0]), "r"(a[1]), "r"(a[2]), "r"(a[3]), "r"(b[0]), "r"(b[1]));
}
__device__ __forceinline__ void addcorr(float* a, const uint32_t* c) {
    float2 x = __half22float2(*(const half2*)&c[0]);
    float2 y = __half22float2(*(const half2*)&c[1]);
    a[0] += x.x; a[1] += x.y; a[2] += y.x; a[3] += y.y;
}
__device__ __forceinline__ void splith(float v, __half& hi, __half& lo) {
    hi = __float2half_rn(v);
    lo = __float2half_rn(v - __half2float(hi));
}
__device__ __forceinline__ uint32_t packh(__half a, __half b) {
    return (uint32_t)__half_as_ushort(a) | ((uint32_t)__half_as_ushort(b) << 16);
}
__device__ __forceinline__ uint32_t smem_u32(const void* p) {
    uint32_t a;
    asm("{ .reg .u64 t; cvta.to.shared.u64 t, %1; cvt.u32.u64 %0, t; }" : "=r"(a) : "l"(p));
    return a;
}

// ======================= precompute (unchanged, known-correct) =======================
__global__ void preK(const float* __restrict__ W1, const float* __restrict__ gates,
                     const float* __restrict__ W2, const float* __restrict__ Wout,
                     const float* __restrict__ Bmat, const float* __restrict__ C,
                     const float* __restrict__ Dm) {
    int bid = blockIdx.x, tid = threadIdx.x;
    if (bid < 640) {
        int e = bid * 256 + tid;
        int row = e / MEAS, k = e % MEAS, n = row >> 7;
        float sc = 1.f;
        if (k < Dd) sc = 1.f / (1.f + expf(-gates[n * Dd + k]));
        splith(W1[e] * sc, g_W1h[e], g_W1l[e]);
    } else if (bid < 768) {
        int e = (bid - 640) * 256 + tid;
        splith(W2[e], g_W2h[e], g_W2l[e]);
    } else if (bid < 1040) {
        int e = (bid - 768) * 256 + tid;
        int d = e / K3, c = e % K3;
        float s = 0.f;
        if (c < 256) {
            int n = c >> 6, j = c & 63;
            const float* wr = Wout + (n * Dd + d) * RH;
            const float* br = Bmat + n * RH * (RH + UD) + j;
            #pragma unroll 8
            for (int r = 0; r < RH; r++) s += wr[r] * br[r * (RH + UD)];
        } else {
            int u = c - 256;
            for (int n = 0; n < NBR; n++) {
                const float* wr = Wout + (n * Dd + d) * RH;
                const float* br = Bmat + n * RH * (RH + UD) + RH + u;
                #pragma unroll 8
                for (int r = 0; r < RH; r++) s += wr[r] * br[r * (RH + UD)];
            }
        }
        splith(s, g_B3h[e], g_B3l[e]);
    } else if (bid < 1040 + NOBS) {
        int o = bid - 1040;
        __shared__ float sCW[256];
        {
            int n = tid >> 6, r = tid & 63;
            const float* cr = C + o * Dd;
            const float* wp = Wout + n * Dd * RH + r;
            float s = 0.f;
            #pragma unroll 8
            for (int d = 0; d < Dd; d++) s += cr[d] * wp[d * RH];
            sCW[tid] = s;
        }
        __syncthreads();
        for (int c = tid; c < K3; c += 256) {
            float v;
            if (c < 256) {
                int n = c >> 6, j = c & 63;
                const float* br = Bmat + n * RH * (RH + UD) + j;
                v = 0.f;
                #pragma unroll 8
                for (int r = 0; r < RH; r++) v += sCW[n * 64 + r] * br[r * (RH + UD)];
            } else {
                int u = c - 256;
                v = Dm[o * UD + u];
                for (int n = 0; n < NBR; n++) {
                    const float* br = Bmat + n * RH * (RH + UD) + RH + u;
                    #pragma unroll 8
                    for (int r = 0; r < RH; r++) v += sCW[n * 64 + r] * br[r * (RH + UD)];
                }
            }
            splith(v, g_B3h[(256 + o) * K3 + c], g_B3l[(256 + o) * K3 + c]);
        }
    } else {
        int e = (bid - 1040 - NOBS) * 256 + tid;
        if (e < (N2 - 256 - NOBS) * K3) {
            int r = 256 + NOBS + e / K3, c = e % K3;
            g_B3h[r * K3 + c] = __float2half(0.f);
            g_B3l[r * K3 + c] = __float2half(0.f);
        }
    }
}

// ======================= main kernel: 512 threads, 4 warps/SMSP =======================
__global__ __launch_bounds__(512, 1) void skolr6(
    const float* __restrict__ z_dyn, const float* __restrict__ z_static,
    const float* __restrict__ dtp,   const float* __restrict__ ut,
    const float* __restrict__ b1g,   const float* __restrict__ gammag,
    const float* __restrict__ betag, const float* __restrict__ b2g,
    float* __restrict__ out)
{
    extern __shared__ char sm[];
    const uint32_t smb = smem_u32(sm);
    const int tid = threadIdx.x, w = tid >> 5, lane = tid & 31;
    const int wm = w >> 2, wn = w & 3;          // 4M x 4N warp grid
    const int g = lane >> 2, t4 = lane & 3;
    const int row0 = blockIdx.x * TM;
    const float dt = dtp[0];

    const int sub = lane >> 3;
    const uint32_t aRow = ((uint32_t)(sub & 1)) * 8 + (lane & 7);
    const uint32_t aCh  = ((uint32_t)(sub >> 1)) * 16;
    const uint32_t bRow = ((uint32_t)(sub >> 1)) * 8 + (lane & 7);
    const uint32_t bCh  = ((uint32_t)(sub & 1)) * 16;

    float* su  = (float*)(sm + OFF_SU);
    float* lns = (float*)(sm + OFF_LN);         // [4][64]
    float* lnq = lns + 256;

    if (tid < 256) {
        int m = tid >> 2, q = tid & 3;
        float4 f = *(const float4*)&ut[(size_t)(row0 + m) * UD + q * 4];
        f.x *= dt; f.y *= dt; f.z *= dt; f.w *= dt;
        *(float4*)&su[m * UD + q * 4] = f;
    }

    // ================= GEMM1 (2 halves of 256 cols) + fused LN/GELU =================
    for (int p = 0; p < 2; p++) {
        float acc[8][4];
        uint32_t corr[8][2];
        #pragma unroll
        for (int i = 0; i < 8; i++) {
            acc[i][0] = acc[i][1] = acc[i][2] = acc[i][3] = 0.f;
            corr[i][0] = corr[i][1] = 0u;
        }

        #define STAGE1(kc_, buf_) do { \
            int _kc = (kc_), _bf = (buf_); \
            if (tid < 256) { int m = tid >> 2, q = tid & 3; \
              float4 f = (_kc < 16) \
                ? *(const float4*)&z_dyn[(size_t)(row0 + m) * Dd + _kc * 16 + q * 4] \
                : *(const float4*)&z_static[(size_t)(row0 + m) * SDIM + (_kc - 16) * 16 + q * 4]; \
              __half h0, l0, h1, l1, h2, l2, h3, l3; \
              splith(f.x, h0, l0); splith(f.y, h1, l1); splith(f.z, h2, l2); splith(f.w, h3, l3); \
              uint2 hp, lp; \
              hp.x = packh(h0, h1); hp.y = packh(h2, h3); \
              lp.x = packh(l0, l1); lp.y = packh(l2, l3); \
              char* ab = sm + OFF_AB + _bf * ABUF + m * 48 + q * 8; \
              *(uint2*)ab = hp; *(uint2*)(ab + APL) = lp; } \
            _Pragma("unroll") \
            for (int t = 0; t < 2; t++) { \
                int comp = tid + t * 512; \
                int n = comp & 255, h16 = (comp >> 8) & 1, pl = comp >> 9; \
                const __half* src = (pl ? g_W1l : g_W1h) + (size_t)(p * 256 + n) * MEAS + _kc * 16 + h16 * 8; \
                uint32_t dst = smb + OFF_BB + _bf * BBUF + pl * BPL + n * 48 + h16 * 16; \
                CPA(dst, src); \
            } \
        } while (0)

        STAGE1(0, 0); CPC();
        for (int kc = 0; kc < 20; kc++) {
            if (kc < 19) { STAGE1(kc + 1, (kc + 1) & 1); CPC(); CPW1(); } else { CPW0(); }
            __syncthreads();
            const int buf = kc & 1;
            uint32_t ah[4], al[4];
            uint32_t aaddr = smb + OFF_AB + buf * ABUF + (wm * 16 + aRow) * 48 + aCh;
            LDSM4(ah, aaddr); LDSM4(al, aaddr + APL);
            uint32_t bbase = smb + OFF_BB + buf * BBUF + (wn * 64 + bRow) * 48 + bCh;
            #pragma unroll
            for (int q = 0; q < 4; q++) {
                uint32_t bh[4], bl[4];
                uint32_t ba = bbase + q * (16 * 48);
                LDSM4(bh, ba); LDSM4(bl, ba + BPL);
                mma_f32(acc[q * 2],      ah, bh);
                mma_f16(corr[q * 2],     ah, bl);
                mma_f16(corr[q * 2],     al, bh);
                mma_f32(acc[q * 2 + 1],  ah, bh + 2);
                mma_f16(corr[q * 2 + 1], ah, bl + 2);
                mma_f16(corr[q * 2 + 1], al, bh + 2);
            }
            __syncthreads();
        }
        #undef STAGE1

        // ---- epilogue: +corr, +b1, LN(128) (t4 shuffles + warp-pair smem), GELU -> H ----
        float s0 = 0.f, q0 = 0.f, s1 = 0.f, q1 = 0.f;
        #pragma unroll
        for (int nt = 0; nt < 8; nt++) {
            addcorr(acc[nt], corr[nt]);
            int c = p * 256 + wn * 64 + nt * 8 + t4 * 2;
            float2 bv = __ldg((const float2*)&b1g[c]);
            acc[nt][0] += bv.x; acc[nt][1] += bv.y; acc[nt][2] += bv.x; acc[nt][3] += bv.y;
            s0 += acc[nt][0] + acc[nt][1];
            q0 = fmaf(acc[nt][0], acc[nt][0], fmaf(acc[nt][1], acc[nt][1], q0));
            s1 += acc[nt][2] + acc[nt][3];
            q1 = fmaf(acc[nt][2], acc[nt][2], fmaf(acc[nt][3], acc[nt][3], q1));
        }
        #pragma unroll
        for (int o = 1; o <= 2; o <<= 1) {
            s0 += __shfl_xor_sync(0xffffffffu, s0, o);
            q0 += __shfl_xor_sync(0xffffffffu, q0, o);
            s1 += __shfl_xor_sync(0xffffffffu, s1, o);
            q1 += __shfl_xor_sync(0xffffffffu, q1, o);
        }
        const int rA = wm * 16 + g, rB = rA + 8;
        if (t4 == 0) {
            lns[wn * 64 + rA] = s0; lnq[wn * 64 + rA] = q0;
            lns[wn * 64 + rB] = s1; lnq[wn * 64 + rB] = q1;
        }
        __syncthreads();
        const int pw = wn ^ 1;
        float s0t = s0 + lns[pw * 64 + rA], q0t = q0 + lnq[pw * 64 + rA];
        float s1t = s1 + lns[pw * 64 + rB], q1t = q1 + lnq[pw * 64 + rB];
        const float mean0 = s0t * (1.f / 128.f);
        const float inv0  = rsqrtf(q0t * (1.f / 128.f) - mean0 * mean0 + 1e-5f);
        const float mean1 = s1t * (1.f / 128.f);
        const float inv1  = rsqrtf(q1t * (1.f / 128.f) - mean1 * mean1 + 1e-5f);
        #pragma unroll
        for (int nt = 0; nt < 8; nt++) {
            int c = p * 256 + wn * 64 + nt * 8 + t4 * 2;
            float2 gv = __ldg((const float2*)&gammag[c]);
            float2 ev = __ldg((const float2*)&betag[c]);
            float t0 = (acc[nt][0] - mean0) * inv0 * gv.x + ev.x;
            float t1 = (acc[nt][1] - mean0) * inv0 * gv.y + ev.y;
            float t2 = (acc[nt][2] - mean1) * inv1 * gv.x + ev.x;
            float t3 = (acc[nt][3] - mean1) * inv1 * gv.y + ev.y;
            t0 = 0.5f * t0 * (1.f + erff(t0 * 0.70710678118654752f));
            t1 = 0.5f * t1 * (1.f + erff(t1 * 0.70710678118654752f));
            t2 = 0.5f * t2 * (1.f + erff(t2 * 0.70710678118654752f));
            t3 = 0.5f * t3 * (1.f + erff(t3 * 0.70710678118654752f));
            __half x0, y0, x1, y1, x2, y2, x3, y3;
            splith(t0, x0, y0); splith(t1, x1, y1); splith(t2, x2, y2); splith(t3, x3, y3);
            *(uint32_t*)(sm + rA * HSTR + c * 2)      = packh(x0, x1);
            *(uint32_t*)(sm + HP + rA * HSTR + c * 2) = packh(y0, y1);
            *(uint32_t*)(sm + rB * HSTR + c * 2)      = packh(x2, x3);
            *(uint32_t*)(sm + HP + rB * HSTR + c * 2) = packh(y2, y3);
        }
        __syncthreads();
    }

    // ================= stage-1: G[n] = H[n] @ W2[n]^T + b2 (warp wn = branch wn) =================
    float acc1[8][4];
    uint32_t corr1[8][2];
    #pragma unroll
    for (int i = 0; i < 8; i++) {
        acc1[i][0] = acc1[i][1] = acc1[i][2] = acc1[i][3] = 0.f;
        corr1[i][0] = corr1[i][1] = 0u;
    }

    #define STAGEW2(kc_, buf_) do { \
        int _kc = (kc_), _bf = (buf_); \
        _Pragma("unroll") \
        for (int t = 0; t < 2; t++) { \
            int comp = tid + t * 512; \
            int n = comp & 255, h16 = (comp >> 8) & 1, pl = comp >> 9; \
            const __half* src = (pl ? g_W2l : g_W2h) + (size_t)n * MH + _kc * 16 + h16 * 8; \
            uint32_t dst = smb + OFF_BB + _bf * BBUF + pl * BPL + n * 48 + h16 * 16; \
            CPA(dst, src); \
        } \
    } while (0)

    STAGEW2(0, 0); CPC();
    for (int kc = 0; kc < 8; kc++) {
        if (kc < 7) { STAGEW2(kc + 1, (kc + 1) & 1); CPC(); CPW1(); } else { CPW0(); }
        __syncthreads();
        const int buf = kc & 1;
        uint32_t ah[4], al[4];
        uint32_t aaddr = smb + (wm * 16 + aRow) * HSTR + wn * 256 + kc * 32 + aCh;
        LDSM4(ah, aaddr); LDSM4(al, aaddr + HP);
        uint32_t bbase = smb + OFF_BB + buf * BBUF + (wn * 64 + bRow) * 48 + bCh;
        #pragma unroll
        for (int q = 0; q < 4; q++) {
            uint32_t bh[4], bl[4];
            uint32_t ba = bbase + q * (16 * 48);
            LDSM4(bh, ba); LDSM4(bl, ba + BPL);
            mma_f32(acc1[q * 2],      ah, bh);
            mma_f16(corr1[q * 2],     ah, bl);
            mma_f16(corr1[q * 2],     al, bh);
            mma_f32(acc1[q * 2 + 1],  ah, bh + 2);
            mma_f16(corr1[q * 2 + 1], ah, bl + 2);
            mma_f16(corr1[q * 2 + 1], al, bh + 2);
        }
        __syncthreads();
    }
    #undef STAGEW2

    // ---- stage-1 epilogue: +corr, +b2, split G -> H cols 0..255; u -> cols 256..271 ----
    {
        const int rA = wm * 16 + g, rB = rA + 8;
        #pragma unroll
        for (int nt = 0; nt < 8; nt++) {
            addcorr(acc1[nt], corr1[nt]);
            int c = wn * 64 + nt * 8 + t4 * 2;
            float2 bv = __ldg((const float2*)&b2g[c]);
            float v0 = acc1[nt][0] + bv.x, v1 = acc1[nt][1] + bv.y;
            float v2 = acc1[nt][2] + bv.x, v3 = acc1[nt][3] + bv.y;
            __half x0, y0, x1, y1, x2, y2, x3, y3;
            splith(v0, x0, y0); splith(v1, x1, y1); splith(v2, x2, y2); splith(v3, x3, y3);
            *(uint32_t*)(sm + rA * HSTR + c * 2)      = packh(x0, x1);
            *(uint32_t*)(sm + HP + rA * HSTR + c * 2) = packh(y0, y1);
            *(uint32_t*)(sm + rB * HSTR + c * 2)      = packh(x2, x3);
            *(uint32_t*)(sm + HP + rB * HSTR + c * 2) = packh(y2, y3);
        }
        for (int idx = tid; idx < TM * UD; idx += 512) {
            int m = idx >> 4, cu = idx & 15;
            __half hi, lo; splith(su[m * UD + cu], hi, lo);
            *(__half*)(sm + m * HSTR + 512 + cu * 2)      = hi;
            *(__half*)(sm + HP + m * HSTR + 512 + cu * 2) = lo;
        }
    }
    __syncthreads();

    // ================= stage-2: [z|yt][64][288] = [G|u][64][272] x B3^T =================
    float acc2[9][4];
    uint32_t corr2[9][2];
    #pragma unroll
    for (int i = 0; i < 9; i++) {
        acc2[i][0] = acc2[i][1] = acc2[i][2] = acc2[i][3] = 0.f;
        corr2[i][0] = corr2[i][1] = 0u;
    }

    #define STAGE3(kc_, buf_) do { \
        int _kc = (kc_), _bf = (buf_); \
        for (int idx = tid; idx < 1152; idx += 512) { \
            int pl = idx / 576, rem = idx % 576, n = rem >> 1, h16 = rem & 1; \
            const __half* src = (pl ? g_B3l : g_B3h) + (size_t)n * K3 + _kc * 16 + h16 * 8; \
            uint32_t dst = smb + OFF_BB + _bf * BBUF + pl * BPL + n * 48 + h16 * 16; \
            CPA(dst, src); \
        } \
    } while (0)

    STAGE3(0, 0); CPC();
    for (int kc = 0; kc < 17; kc++) {
        if (kc < 16) { STAGE3(kc + 1, (kc + 1) & 1); CPC(); CPW1(); } else { CPW0(); }
        __syncthreads();
        const int buf = kc & 1;
        uint32_t ah[4], al[4];
        uint32_t aaddr = smb + (wm * 16 + aRow) * HSTR + kc * 32 + aCh;
        LDSM4(ah, aaddr); LDSM4(al, aaddr + HP);
        uint32_t bbase = smb + OFF_BB + buf * BBUF + (wn * 72 + bRow) * 48 + bCh;
        #pragma unroll
        for (int q = 0; q < 4; q++) {
            uint32_t bh[4], bl[4];
            uint32_t ba = bbase + q * (16 * 48);
            LDSM4(bh, ba); LDSM4(bl, ba + BPL);
            mma_f32(acc2[q * 2],      ah, bh);
            mma_f16(corr2[q * 2],     ah, bl);
            mma_f16(corr2[q * 2],     al, bh);
            mma_f32(acc2[q * 2 + 1],  ah, bh + 2);
            mma_f16(corr2[q * 2 + 1], ah, bl + 2);
            mma_f16(corr2[q * 2 + 1], al, bh + 2);
        }
        {   // remainder 8-row tile (rows wn*72+64 .. +71)
            uint32_t ra = smb + OFF_BB + buf * BBUF +
                          (wn * 72 + 64 + (lane & 7)) * 48 + ((lane >> 3) & 1) * 16;
            uint32_t bh[2], bl[2];
            LDSM2(bh, ra); LDSM2(bl, ra + BPL);
            mma_f32(acc2[8],  ah, bh);
            mma_f16(corr2[8], ah, bl);
            mma_f16(corr2[8], al, bh);
        }
        __syncthreads();
    }
    #undef STAGE3

    // ---- epilogue: write z_next and yt (biases fully folded) ----
    float* out_yt = out + (size_t)BSZ * Dd;
    #pragma unroll
    for (int nt = 0; nt < 9; nt++) {
        addcorr(acc2[nt], corr2[nt]);
        const int n0 = wn * 72 + nt * 8 + t4 * 2;
        const int r = wm * 16 + g;
        float v0 = acc2[nt][0], v1 = acc2[nt][1];
        float v2 = acc2[nt][2], v3 = acc2[nt][3];
        if (n0 < Dd) {
            *(float2*)&out[(size_t)(row0 + r) * Dd + n0]     = make_float2(v0, v1);
            *(float2*)&out[(size_t)(row0 + r + 8) * Dd + n0] = make_float2(v2, v3);
        } else {
            const int o = n0 - Dd;
            if (o < NOBS)     { out_yt[(size_t)(row0 + r) * NOBS + o]     = v0;
                                out_yt[(size_t)(row0 + r + 8) * NOBS + o] = v2; }
            if (o + 1 < NOBS) { out_yt[(size_t)(row0 + r) * NOBS + o + 1]     = v1;
                                out_yt[(size_t)(row0 + r + 8) * NOBS + o + 1] = v3; }
        }
    }
}

extern "C" void kernel_launch(void* const* d_in, const int* in_sizes, int n_in,
                              void* d_out, int out_size) {
    const float* z_dyn    = (const float*)d_in[0];
    const float* z_static = (const float*)d_in[1];
    const float* dt       = (const float*)d_in[2];
    const float* ut       = (const float*)d_in[3];
    const float* gates    = (const float*)d_in[4];
    const float* W1       = (const float*)d_in[5];
    const float* b1       = (const float*)d_in[6];
    const float* gamma    = (const float*)d_in[7];
    const float* beta     = (const float*)d_in[8];
    const float* W2       = (const float*)d_in[9];
    const float* b2       = (const float*)d_in[10];
    const float* Bmat     = (const float*)d_in[13];
    const float* Wout     = (const float*)d_in[14];
    const float* Cmat     = (const float*)d_in[15];
    const float* Dm       = (const float*)d_in[16];
    float* out = (float*)d_out;

    preK<<<1040 + NOBS + 8, 256>>>(W1, gates, W2, Wout, Bmat, Cmat, Dm);

    cudaFuncSetAttribute(skolr6, cudaFuncAttributeMaxDynamicSharedMemorySize, SMEM_TOTAL);
    skolr6<<<BSZ / TM, 512, SMEM_TOTAL>>>(z_dyn, z_static, dt, ut, b1, gamma, beta, b2, out);
}